// round 13
// baseline (speedup 1.0000x reference)
#include <cuda_runtime.h>
#include <cstdint>
#include <math.h>

#define V 32000
#define E 256
#define H 512
#define B 512
#define S 256
#define G3 (3*H)

#define GRID 148
#define NT   512

// ---------------- device scratch (static globals: no allocs allowed) --------
__device__ float g_h[B*H];
__device__ float g_x[B*E];
__device__ float g_gi[B*G3];
__device__ float g_gh[B*G3];
__device__ float g_logits[B*V];       // 65.5 MB
__device__ unsigned g_stepkeys[S*2];
__device__ unsigned g_barrier_count;

// ---------------- Threefry-2x32 (exactly JAX's) -----------------------------
__device__ __forceinline__ void tf2x32(uint32_t k0, uint32_t k1,
                                       uint32_t x0, uint32_t x1,
                                       uint32_t& o0, uint32_t& o1) {
    uint32_t k2 = k0 ^ k1 ^ 0x1BD11BDAu;
    x0 += k0; x1 += k1;
#define TFRND(r) { x0 += x1; x1 = __funnelshift_l(x1, x1, r); x1 ^= x0; }
    TFRND(13) TFRND(15) TFRND(26) TFRND(6)
    x0 += k1; x1 += k2 + 1u;
    TFRND(17) TFRND(29) TFRND(16) TFRND(24)
    x0 += k2; x1 += k0 + 2u;
    TFRND(13) TFRND(15) TFRND(26) TFRND(6)
    x0 += k0; x1 += k1 + 3u;
    TFRND(17) TFRND(29) TFRND(16) TFRND(24)
    x0 += k1; x1 += k2 + 4u;
    TFRND(13) TFRND(15) TFRND(26) TFRND(6)
    x0 += k2; x1 += k0 + 5u;
#undef TFRND
    o0 = x0; o1 = x1;
}

__device__ __forceinline__ float u01(uint32_t bits) {
    return __uint_as_float((bits >> 9) | 0x3f800000u) - 1.0f;
}

// ---------------- init: h=0, x=emb[0] broadcast, per-step keys --------------
// jax_threefry_partitionable=True: split(key(42),S): key_t = tf((0,42); ctr=t)
__global__ void init_kernel(const float* __restrict__ emb) {
    int idx = blockIdx.x * blockDim.x + threadIdx.x;
    if (idx == 0) g_barrier_count = 0u;
    if (idx < B*H) g_h[idx] = 0.0f;
    if (idx < B*E) g_x[idx] = emb[idx % E];   // start token id 0
    if (idx < S) {
        uint32_t o0, o1;
        tf2x32(0u, 42u, 0u, (uint32_t)idx, o0, o1);
        g_stepkeys[2*idx]   = o0;
        g_stepkeys[2*idx+1] = o1;
    }
}

// ---------------- grid-wide software barrier --------------------------------
__device__ __forceinline__ void gsync(unsigned &epoch) {
    epoch += 1u;
    __syncthreads();
    if (threadIdx.x == 0) {
        __threadfence();               // release prior global writes
        atomicAdd(&g_barrier_count, 1u);
        unsigned tgt = epoch * GRID;
        while (atomicAdd(&g_barrier_count, 0u) < tgt) __nanosleep(64);
        __threadfence();               // acquire
    }
    __syncthreads();
}

// ---------------- 64x64 tile SGEMM (gates), 512 thr, 2x4/thread -------------
// Bit-exact vs any tiling: each output accumulates k=0..K-1 sequentially via
// fmaf into one register, then + bias.
__device__ void gemm_tile64(const float* __restrict__ A, const float* __restrict__ W,
                            const float* __restrict__ bias, float* __restrict__ C,
                            int N, int K, int bm, int bn, float* As, float* Bs) {
    const int tid = threadIdx.x;
    const int tx = tid % 16, ty = tid / 16;   // ty in [0,32): 2 rows each
    float acc[2][4];
#pragma unroll
    for (int i = 0; i < 2; i++)
#pragma unroll
        for (int j = 0; j < 4; j++) acc[i][j] = 0.0f;

    const int lr = (tid & 255) / 4, lc = tid & 3;   // loader slot
    const bool loadA = tid < 256;
#pragma unroll 1
    for (int k0 = 0; k0 < K; k0 += 16) {
        {
            const float* src = loadA
                ? (A + (size_t)(bm + lr) * K + k0 + lc * 4)
                : (W + (size_t)(bn + lr) * K + k0 + lc * 4);
            float4 v = *(const float4*)src;
            float* dst = loadA ? As : Bs;
            dst[(lc*4+0)*64 + lr] = v.x; dst[(lc*4+1)*64 + lr] = v.y;
            dst[(lc*4+2)*64 + lr] = v.z; dst[(lc*4+3)*64 + lr] = v.w;
        }
        __syncthreads();
#pragma unroll
        for (int kk = 0; kk < 16; kk++) {
            float2 a = *(const float2*)&As[kk*64 + ty*2];
            float4 b = *(const float4*)&Bs[kk*64 + tx*4];
            float ar[2] = {a.x, a.y};
            float br[4] = {b.x, b.y, b.z, b.w};
#pragma unroll
            for (int i = 0; i < 2; i++)
#pragma unroll
                for (int j = 0; j < 4; j++) acc[i][j] = fmaf(ar[i], br[j], acc[i][j]);
        }
        __syncthreads();
    }
#pragma unroll
    for (int i = 0; i < 2; i++) {
        int m = bm + ty*2 + i;
#pragma unroll
        for (int j = 0; j < 4; j++) {
            int n = bn + tx*4 + j;
            C[(size_t)m * N + n] = acc[i][j] + bias[n];
        }
    }
}

// ---------------- 128x128 tile SGEMM (logits), 512 thr, 4x8/thread ----------
__device__ void gemm_tile128(const float* __restrict__ A, const float* __restrict__ W,
                             const float* __restrict__ bias, float* __restrict__ C,
                             int bm, int bn, float* As, float* Bs) {
    const int K = H;                          // 512
    const int tid = threadIdx.x;
    const int tx = tid % 16, ty = tid / 16;   // ty in [0,32): 4 rows each
    float acc[4][8];
#pragma unroll
    for (int i = 0; i < 4; i++)
#pragma unroll
        for (int j = 0; j < 8; j++) acc[i][j] = 0.0f;

    const int r0 = tid / 4, c0 = tid % 4;     // loader: 128 rows x 4 float4

    {   // preload k-tile 0
        float4 a0 = *(const float4*)(A + (size_t)(bm + r0) * K + c0 * 4);
        float4 w0 = *(const float4*)(W + (size_t)(bn + r0) * K + c0 * 4);
        As[(c0*4+0)*128 + r0] = a0.x; As[(c0*4+1)*128 + r0] = a0.y;
        As[(c0*4+2)*128 + r0] = a0.z; As[(c0*4+3)*128 + r0] = a0.w;
        Bs[(c0*4+0)*128 + r0] = w0.x; Bs[(c0*4+1)*128 + r0] = w0.y;
        Bs[(c0*4+2)*128 + r0] = w0.z; Bs[(c0*4+3)*128 + r0] = w0.w;
    }
    __syncthreads();

#pragma unroll 1
    for (int k0 = 0; k0 < K; k0 += 16) {
        float4 pa, pb;
        const bool more = (k0 + 16) < K;
        if (more) {
            pa = *(const float4*)(A + (size_t)(bm + r0) * K + k0 + 16 + c0 * 4);
            pb = *(const float4*)(W + (size_t)(bn + r0) * K + k0 + 16 + c0 * 4);
        }
#pragma unroll
        for (int kk = 0; kk < 16; kk++) {
            float4 a0 = *(const float4*)&As[kk*128 + ty*4];
            float4 b0 = *(const float4*)&Bs[kk*128 + tx*8];
            float4 b1 = *(const float4*)&Bs[kk*128 + tx*8 + 4];
            float ar[4] = {a0.x,a0.y,a0.z,a0.w};
            float br[8] = {b0.x,b0.y,b0.z,b0.w,b1.x,b1.y,b1.z,b1.w};
#pragma unroll
            for (int i = 0; i < 4; i++)
#pragma unroll
                for (int j = 0; j < 8; j++) acc[i][j] = fmaf(ar[i], br[j], acc[i][j]);
        }
        __syncthreads();
        if (more) {
            As[(c0*4+0)*128 + r0] = pa.x; As[(c0*4+1)*128 + r0] = pa.y;
            As[(c0*4+2)*128 + r0] = pa.z; As[(c0*4+3)*128 + r0] = pa.w;
            Bs[(c0*4+0)*128 + r0] = pb.x; Bs[(c0*4+1)*128 + r0] = pb.y;
            Bs[(c0*4+2)*128 + r0] = pb.z; Bs[(c0*4+3)*128 + r0] = pb.w;
        }
        __syncthreads();
    }
#pragma unroll
    for (int i = 0; i < 4; i++) {
        int m = bm + ty*4 + i;
#pragma unroll
        for (int j = 0; j < 8; j++) {
            int n = bn + tx*8 + j;
            C[(size_t)m * V + n] = acc[i][j] + bias[n];
        }
    }
}

// ---------------- persistent kernel -----------------------------------------
__global__ __launch_bounds__(NT, 1)
void actor_persistent(const float* __restrict__ emb,
                      const float* __restrict__ w_ih, const float* __restrict__ w_hh,
                      const float* __restrict__ b_ih, const float* __restrict__ b_hh,
                      const float* __restrict__ w_out, const float* __restrict__ b_out,
                      float* __restrict__ out) {
    __shared__ __align__(16) float sh[4096];   // As = sh, Bs = sh+2048
    __shared__ float sv[NT];
    __shared__ int   si[NT];

    const int tid = threadIdx.x;
    unsigned epoch = 0;
    const float NLU  = -10.373491181781864f;   // -float32(log(32000))
    const float TINY = 1.1754943508222875e-38f;

    for (int t = 0; t < S; t++) {
        // ---- Phase A: gate GEMMs gi = x@w_ih^T+b_ih, gh = h@w_hh^T+b_hh ----
        for (int tile = blockIdx.x; tile < 384; tile += GRID) {
            if (tile < 192) {
                int bm = (tile / 24) * 64, bn = (tile % 24) * 64;
                gemm_tile64(g_x, w_ih, b_ih, g_gi, G3, E, bm, bn, sh, sh + 2048);
            } else {
                int tt = tile - 192;
                int bm = (tt / 24) * 64, bn = (tt % 24) * 64;
                gemm_tile64(g_h, w_hh, b_hh, g_gh, G3, H, bm, bn, sh, sh + 2048);
            }
        }
        gsync(epoch);

        // ---- Phase B: GRU combine (elementwise, exact) ----
        for (int idx = blockIdx.x * NT + tid; idx < B*H; idx += GRID * NT) {
            int b = idx / H, j = idx % H;
            const float* gi = g_gi + (size_t)b * G3;
            const float* gh = g_gh + (size_t)b * G3;
            float i_r = gi[j],        h_r = gh[j];
            float i_z = gi[H + j],    h_z = gh[H + j];
            float i_n = gi[2*H + j],  h_n = gh[2*H + j];
            float r = 1.0f / (1.0f + expf(-(i_r + h_r)));
            float z = 1.0f / (1.0f + expf(-(i_z + h_z)));
            float n = tanhf(i_n + r * h_n);
            float h_old = g_h[idx];
            g_h[idx] = (1.0f - z) * n + z * h_old;
        }
        gsync(epoch);

        // ---- Phase C: logits GEMM (512 x 32000, K=512) ----
        for (int tile = blockIdx.x; tile < 1000; tile += GRID) {
            int bm = (tile % 4) * 128, bn = (tile / 4) * 128;
            gemm_tile128(g_h, w_out, b_out, g_logits, bm, bn, sh, sh + 2048);
        }
        gsync(epoch);

        // ---- Phase D: per-row stats + gumbel sample (foldlike RNG) ----
        uint32_t kt0 = g_stepkeys[2*t], kt1 = g_stepkeys[2*t+1];
        uint32_t ke0, ke1, kg0, kg1;
        tf2x32(kt0, kt1, 0u, 0u, ke0, ke1);
        tf2x32(kt0, kt1, 0u, 1u, kg0, kg1);
        float eps = 0.05f + 0.95f * expf(-4.0f * (float)t / 10000.0f);

        for (int row = blockIdx.x; row < B; row += GRID) {
            const float* rowp = g_logits + (size_t)row * V;
            // pass 1: row max over all 512 threads (max is order-exact)
            float m = -INFINITY;
            for (int v = tid; v < V; v += NT) m = fmaxf(m, rowp[v]);
            sv[tid] = m; __syncthreads();
            for (int s = NT/2; s > 0; s >>= 1) {
                if (tid < s) sv[tid] = fmaxf(sv[tid], sv[tid + s]);
                __syncthreads();
            }
            float rm = sv[0]; __syncthreads();
            // pass 2: sum exp — RESTRICTED to 256 threads, stride 256, same
            // tree as the verified kernel => ls bit-identical
            if (tid < 256) {
                float sum = 0.0f;
                for (int v = tid; v < V; v += 256) sum += expf(rowp[v] - rm);
                sv[tid] = sum;
            }
            __syncthreads();
            for (int s = 128; s > 0; s >>= 1) {
                if (tid < s) sv[tid] += sv[tid + s];
                __syncthreads();
            }
            float ls = logf(sv[0]); __syncthreads();
            // eps draw for this row: bits = o0^o1 of tf(ke; 0, row)
            uint32_t db0, db1;
            tf2x32(ke0, ke1, 0u, (uint32_t)row, db0, db1);
            int draw = (eps >= u01(db0 ^ db1)) ? 1 : 0;
            // pass 3: gumbel + argmax over all 512 threads (elementwise exact;
            // min-index tie-break preserved)
            float best = -INFINITY; int bi = V;
            for (int v = tid; v < V; v += NT) {
                uint32_t n = (uint32_t)row * (uint32_t)V + (uint32_t)v;
                uint32_t o0, o1;
                tf2x32(kg0, kg1, 0u, n, o0, o1);
                float u = u01(o0 ^ o1); if (u == 0.0f) u = TINY;
                float g = -logf(-logf(u));
                float val = (draw ? NLU : ((rowp[v] - rm) - ls)) + g;
                if (val > best) { best = val; bi = v; }
            }
            sv[tid] = best; si[tid] = bi; __syncthreads();
            for (int s = NT/2; s > 0; s >>= 1) {
                if (tid < s) {
                    float v2 = sv[tid+s]; int i2 = si[tid+s];
                    if (v2 > sv[tid] || (v2 == sv[tid] && i2 < si[tid])) { sv[tid]=v2; si[tid]=i2; }
                }
                __syncthreads();
            }
            int samp = si[0];
            if (tid == 0) {
                float lp = (rowp[samp] - rm) - ls;
                out[(size_t)row * S + t]                   = (float)samp;
                out[(size_t)B * S + (size_t)row * S + t]   = lp;
            }
            // next-step input embedding (E == 256)
            if (tid < E) g_x[(size_t)row * E + tid] = emb[(size_t)samp * E + tid];
            __syncthreads();
        }
        gsync(epoch);
    }
}

// ---------------- launch: exactly 2 graph nodes -----------------------------
extern "C" void kernel_launch(void* const* d_in, const int* in_sizes, int n_in,
                              void* d_out, int out_size) {
    const float* emb   = (const float*)d_in[0];
    const float* w_ih  = (const float*)d_in[1];
    const float* w_hh  = (const float*)d_in[2];
    const float* b_ih  = (const float*)d_in[3];
    const float* b_hh  = (const float*)d_in[4];
    const float* w_out = (const float*)d_in[5];
    const float* b_out = (const float*)d_in[6];
    float* out = (float*)d_out;

    init_kernel<<<(B*H + 511)/512, 512>>>(emb);
    actor_persistent<<<GRID, NT>>>(emb, w_ih, w_hh, b_ih, b_hh, w_out, b_out, out);
}

// round 14
// speedup vs baseline: 1.2857x; 1.2857x over previous
#include <cuda_runtime.h>
#include <cstdint>
#include <math.h>

#define V 32000
#define E 256
#define H 512
#define B 512
#define S 256
#define G3 (3*H)

#define GRID 148
#define NT   256

// ---------------- device scratch (static globals: no allocs allowed) --------
__device__ float g_h[B*H];
__device__ float g_x[B*E];
__device__ float g_gi[B*G3];
__device__ float g_gh[B*G3];
__device__ float g_logits[B*V];       // 65.5 MB
__device__ unsigned g_stepkeys[S*2];
__device__ unsigned g_barrier_count;

// ---------------- Threefry-2x32 (exactly JAX's) -----------------------------
__device__ __forceinline__ void tf2x32(uint32_t k0, uint32_t k1,
                                       uint32_t x0, uint32_t x1,
                                       uint32_t& o0, uint32_t& o1) {
    uint32_t k2 = k0 ^ k1 ^ 0x1BD11BDAu;
    x0 += k0; x1 += k1;
#define TFRND(r) { x0 += x1; x1 = __funnelshift_l(x1, x1, r); x1 ^= x0; }
    TFRND(13) TFRND(15) TFRND(26) TFRND(6)
    x0 += k1; x1 += k2 + 1u;
    TFRND(17) TFRND(29) TFRND(16) TFRND(24)
    x0 += k2; x1 += k0 + 2u;
    TFRND(13) TFRND(15) TFRND(26) TFRND(6)
    x0 += k0; x1 += k1 + 3u;
    TFRND(17) TFRND(29) TFRND(16) TFRND(24)
    x0 += k1; x1 += k2 + 4u;
    TFRND(13) TFRND(15) TFRND(26) TFRND(6)
    x0 += k2; x1 += k0 + 5u;
#undef TFRND
    o0 = x0; o1 = x1;
}

__device__ __forceinline__ float u01(uint32_t bits) {
    return __uint_as_float((bits >> 9) | 0x3f800000u) - 1.0f;
}

// ---------------- init: h=0, x=emb[0] broadcast, per-step keys --------------
// jax_threefry_partitionable=True: split(key(42),S): key_t = tf((0,42); ctr=t)
__global__ void init_kernel(const float* __restrict__ emb) {
    int idx = blockIdx.x * blockDim.x + threadIdx.x;
    if (idx == 0) g_barrier_count = 0u;
    if (idx < B*H) g_h[idx] = 0.0f;
    if (idx < B*E) g_x[idx] = emb[idx % E];   // start token id 0
    if (idx < S) {
        uint32_t o0, o1;
        tf2x32(0u, 42u, 0u, (uint32_t)idx, o0, o1);
        g_stepkeys[2*idx]   = o0;
        g_stepkeys[2*idx+1] = o1;
    }
}

// ---------------- grid-wide software barrier --------------------------------
__device__ __forceinline__ void gsync(unsigned &epoch) {
    epoch += 1u;
    __syncthreads();
    if (threadIdx.x == 0) {
        __threadfence();               // release prior global writes
        atomicAdd(&g_barrier_count, 1u);
        unsigned tgt = epoch * GRID;
        while (atomicAdd(&g_barrier_count, 0u) < tgt) __nanosleep(64);
        __threadfence();               // acquire
    }
    __syncthreads();
}

// ---------------- 64x64 tile SGEMM (gates), 256 thr, 4x4/thread (R9) --------
__device__ void gemm_tile64(const float* __restrict__ A, const float* __restrict__ W,
                            const float* __restrict__ bias, float* __restrict__ C,
                            int N, int K, int bm, int bn, float* As, float* Bs) {
    const int tid = threadIdx.x;
    const int tx = tid % 16, ty = tid / 16;
    float acc[4][4];
#pragma unroll
    for (int i = 0; i < 4; i++)
#pragma unroll
        for (int j = 0; j < 4; j++) acc[i][j] = 0.0f;

    const int r = tid / 4, c4 = tid % 4;      // 64 rows x 4 float4-cols
#pragma unroll 1
    for (int k0 = 0; k0 < K; k0 += 16) {
        {
            float4 v = *(const float4*)(A + (size_t)(bm + r) * K + k0 + c4 * 4);
            As[(c4*4+0)*64 + r] = v.x; As[(c4*4+1)*64 + r] = v.y;
            As[(c4*4+2)*64 + r] = v.z; As[(c4*4+3)*64 + r] = v.w;
            float4 w = *(const float4*)(W + (size_t)(bn + r) * K + k0 + c4 * 4);
            Bs[(c4*4+0)*64 + r] = w.x; Bs[(c4*4+1)*64 + r] = w.y;
            Bs[(c4*4+2)*64 + r] = w.z; Bs[(c4*4+3)*64 + r] = w.w;
        }
        __syncthreads();
#pragma unroll
        for (int kk = 0; kk < 16; kk++) {
            float4 a = *(const float4*)&As[kk*64 + ty*4];
            float4 b = *(const float4*)&Bs[kk*64 + tx*4];
            float ar[4] = {a.x, a.y, a.z, a.w};
            float br[4] = {b.x, b.y, b.z, b.w};
#pragma unroll
            for (int i = 0; i < 4; i++)
#pragma unroll
                for (int j = 0; j < 4; j++) acc[i][j] = fmaf(ar[i], br[j], acc[i][j]);
        }
        __syncthreads();
    }
#pragma unroll
    for (int i = 0; i < 4; i++) {
        int m = bm + ty*4 + i;
#pragma unroll
        for (int j = 0; j < 4; j++) {
            int n = bn + tx*4 + j;
            C[(size_t)m * N + n] = acc[i][j] + bias[n];
        }
    }
}

// ---------------- 128x128 tile SGEMM (logits) -------------------------------
// 256 thr, 8x8/thread, DOUBLE-BUFFERED smem (1 sync per k-tile) + register
// fragment pipelining (kk+1 fragments loaded during kk FMAs).
// Accumulation order per output element identical to prior rounds.
__device__ void gemm_tile128(const float* __restrict__ A, const float* __restrict__ W,
                             const float* __restrict__ bias, float* __restrict__ C,
                             int bm, int bn,
                             float* As0, float* Bs0, float* As1, float* Bs1) {
    const int K = H;                          // 512
    const int tid = threadIdx.x;
    const int tx = tid % 16, ty = tid / 16;   // each thread 8x8
    float acc[8][8];
#pragma unroll
    for (int i = 0; i < 8; i++)
#pragma unroll
        for (int j = 0; j < 8; j++) acc[i][j] = 0.0f;

    const int r0 = tid / 4, c0 = tid % 4;
    const int r1 = r0 + 64;

    {   // preload k-tile 0 into buffer 0
        float4 a0 = *(const float4*)(A + (size_t)(bm + r0) * K + c0 * 4);
        float4 a1 = *(const float4*)(A + (size_t)(bm + r1) * K + c0 * 4);
        float4 w0 = *(const float4*)(W + (size_t)(bn + r0) * K + c0 * 4);
        float4 w1 = *(const float4*)(W + (size_t)(bn + r1) * K + c0 * 4);
        As0[(c0*4+0)*128 + r0] = a0.x; As0[(c0*4+1)*128 + r0] = a0.y;
        As0[(c0*4+2)*128 + r0] = a0.z; As0[(c0*4+3)*128 + r0] = a0.w;
        As0[(c0*4+0)*128 + r1] = a1.x; As0[(c0*4+1)*128 + r1] = a1.y;
        As0[(c0*4+2)*128 + r1] = a1.z; As0[(c0*4+3)*128 + r1] = a1.w;
        Bs0[(c0*4+0)*128 + r0] = w0.x; Bs0[(c0*4+1)*128 + r0] = w0.y;
        Bs0[(c0*4+2)*128 + r0] = w0.z; Bs0[(c0*4+3)*128 + r0] = w0.w;
        Bs0[(c0*4+0)*128 + r1] = w1.x; Bs0[(c0*4+1)*128 + r1] = w1.y;
        Bs0[(c0*4+2)*128 + r1] = w1.z; Bs0[(c0*4+3)*128 + r1] = w1.w;
    }
    __syncthreads();

    float* Ac = As0; float* Bc = Bs0;         // current compute buffers
    float* An = As1; float* Bn = Bs1;         // next (fill) buffers

#pragma unroll 1
    for (int k0 = 0; k0 < K; k0 += 16) {
        float4 pa0, pa1, pb0, pb1;
        const bool more = (k0 + 16) < K;
        if (more) {
            pa0 = *(const float4*)(A + (size_t)(bm + r0) * K + k0 + 16 + c0 * 4);
            pa1 = *(const float4*)(A + (size_t)(bm + r1) * K + k0 + 16 + c0 * 4);
            pb0 = *(const float4*)(W + (size_t)(bn + r0) * K + k0 + 16 + c0 * 4);
            pb1 = *(const float4*)(W + (size_t)(bn + r1) * K + k0 + 16 + c0 * 4);
        }
        // register fragment pipeline over the 16 kk slices of this k-tile
        float fa[2][8], fb[2][8];
        {   // load kk = 0 fragments
            float4 x0 = *(const float4*)&Ac[0*128 + ty*8];
            float4 x1 = *(const float4*)&Ac[0*128 + ty*8 + 4];
            float4 y0 = *(const float4*)&Bc[0*128 + tx*8];
            float4 y1 = *(const float4*)&Bc[0*128 + tx*8 + 4];
            fa[0][0]=x0.x; fa[0][1]=x0.y; fa[0][2]=x0.z; fa[0][3]=x0.w;
            fa[0][4]=x1.x; fa[0][5]=x1.y; fa[0][6]=x1.z; fa[0][7]=x1.w;
            fb[0][0]=y0.x; fb[0][1]=y0.y; fb[0][2]=y0.z; fb[0][3]=y0.w;
            fb[0][4]=y1.x; fb[0][5]=y1.y; fb[0][6]=y1.z; fb[0][7]=y1.w;
        }
#pragma unroll
        for (int kk = 0; kk < 16; kk++) {
            const int cur = kk & 1, nxt = cur ^ 1;
            if (kk < 15) {   // prefetch kk+1 fragments while FMAs of kk issue
                float4 x0 = *(const float4*)&Ac[(kk+1)*128 + ty*8];
                float4 x1 = *(const float4*)&Ac[(kk+1)*128 + ty*8 + 4];
                float4 y0 = *(const float4*)&Bc[(kk+1)*128 + tx*8];
                float4 y1 = *(const float4*)&Bc[(kk+1)*128 + tx*8 + 4];
                fa[nxt][0]=x0.x; fa[nxt][1]=x0.y; fa[nxt][2]=x0.z; fa[nxt][3]=x0.w;
                fa[nxt][4]=x1.x; fa[nxt][5]=x1.y; fa[nxt][6]=x1.z; fa[nxt][7]=x1.w;
                fb[nxt][0]=y0.x; fb[nxt][1]=y0.y; fb[nxt][2]=y0.z; fb[nxt][3]=y0.w;
                fb[nxt][4]=y1.x; fb[nxt][5]=y1.y; fb[nxt][6]=y1.z; fb[nxt][7]=y1.w;
            }
#pragma unroll
            for (int i = 0; i < 8; i++)
#pragma unroll
                for (int j = 0; j < 8; j++)
                    acc[i][j] = fmaf(fa[cur][i], fb[cur][j], acc[i][j]);
        }
        // fill the other buffer for the next k-tile (no reader conflict)
        if (more) {
            An[(c0*4+0)*128 + r0] = pa0.x; An[(c0*4+1)*128 + r0] = pa0.y;
            An[(c0*4+2)*128 + r0] = pa0.z; An[(c0*4+3)*128 + r0] = pa0.w;
            An[(c0*4+0)*128 + r1] = pa1.x; An[(c0*4+1)*128 + r1] = pa1.y;
            An[(c0*4+2)*128 + r1] = pa1.z; An[(c0*4+3)*128 + r1] = pa1.w;
            Bn[(c0*4+0)*128 + r0] = pb0.x; Bn[(c0*4+1)*128 + r0] = pb0.y;
            Bn[(c0*4+2)*128 + r0] = pb0.z; Bn[(c0*4+3)*128 + r0] = pb0.w;
            Bn[(c0*4+0)*128 + r1] = pb1.x; Bn[(c0*4+1)*128 + r1] = pb1.y;
            Bn[(c0*4+2)*128 + r1] = pb1.z; Bn[(c0*4+3)*128 + r1] = pb1.w;
        }
        __syncthreads();   // single barrier per k-tile
        float* tA = Ac; Ac = An; An = tA;
        float* tB = Bc; Bc = Bn; Bn = tB;
    }
#pragma unroll
    for (int i = 0; i < 8; i++) {
        int m = bm + ty*8 + i;
#pragma unroll
        for (int j = 0; j < 8; j++) {
            int n = bn + tx*8 + j;
            C[(size_t)m * V + n] = acc[i][j] + bias[n];
        }
    }
}

// ---------------- persistent kernel -----------------------------------------
__global__ __launch_bounds__(NT, 1)
void actor_persistent(const float* __restrict__ emb,
                      const float* __restrict__ w_ih, const float* __restrict__ w_hh,
                      const float* __restrict__ b_ih, const float* __restrict__ b_hh,
                      const float* __restrict__ w_out, const float* __restrict__ b_out,
                      float* __restrict__ out) {
    __shared__ __align__(16) float sA0[2048];
    __shared__ __align__(16) float sB0[2048];
    __shared__ __align__(16) float sA1[2048];
    __shared__ __align__(16) float sB1[2048];
    __shared__ float sv[NT];
    __shared__ int   si[NT];

    const int tid = threadIdx.x;
    unsigned epoch = 0;
    const float NLU  = -10.373491181781864f;   // -float32(log(32000))
    const float TINY = 1.1754943508222875e-38f;

    for (int t = 0; t < S; t++) {
        // ---- Phase A: gate GEMMs gi = x@w_ih^T+b_ih, gh = h@w_hh^T+b_hh ----
        for (int tile = blockIdx.x; tile < 384; tile += GRID) {
            if (tile < 192) {
                int bm = (tile / 24) * 64, bn = (tile % 24) * 64;
                gemm_tile64(g_x, w_ih, b_ih, g_gi, G3, E, bm, bn, sA0, sB0);
            } else {
                int tt = tile - 192;
                int bm = (tt / 24) * 64, bn = (tt % 24) * 64;
                gemm_tile64(g_h, w_hh, b_hh, g_gh, G3, H, bm, bn, sA0, sB0);
            }
        }
        gsync(epoch);

        // ---- Phase B: GRU combine (elementwise, exact) ----
        for (int idx = blockIdx.x * NT + tid; idx < B*H; idx += GRID * NT) {
            int b = idx / H, j = idx % H;
            const float* gi = g_gi + (size_t)b * G3;
            const float* gh = g_gh + (size_t)b * G3;
            float i_r = gi[j],        h_r = gh[j];
            float i_z = gi[H + j],    h_z = gh[H + j];
            float i_n = gi[2*H + j],  h_n = gh[2*H + j];
            float r = 1.0f / (1.0f + expf(-(i_r + h_r)));
            float z = 1.0f / (1.0f + expf(-(i_z + h_z)));
            float n = tanhf(i_n + r * h_n);
            float h_old = g_h[idx];
            g_h[idx] = (1.0f - z) * n + z * h_old;
        }
        gsync(epoch);

        // ---- Phase C: logits GEMM (512 x 32000, K=512) ----
        for (int tile = blockIdx.x; tile < 1000; tile += GRID) {
            int bm = (tile % 4) * 128, bn = (tile / 4) * 128;
            gemm_tile128(g_h, w_out, b_out, g_logits, bm, bn, sA0, sB0, sA1, sB1);
        }
        gsync(epoch);

        // ---- Phase D: per-row stats + gumbel sample (foldlike RNG) ----
        uint32_t kt0 = g_stepkeys[2*t], kt1 = g_stepkeys[2*t+1];
        uint32_t ke0, ke1, kg0, kg1;
        tf2x32(kt0, kt1, 0u, 0u, ke0, ke1);
        tf2x32(kt0, kt1, 0u, 1u, kg0, kg1);
        float eps = 0.05f + 0.95f * expf(-4.0f * (float)t / 10000.0f);

        for (int row = blockIdx.x; row < B; row += GRID) {
            const float* rowp = g_logits + (size_t)row * V;
            // pass 1: row max
            float m = -INFINITY;
            for (int v = tid; v < V; v += NT) m = fmaxf(m, rowp[v]);
            sv[tid] = m; __syncthreads();
            for (int s = 128; s > 0; s >>= 1) {
                if (tid < s) sv[tid] = fmaxf(sv[tid], sv[tid + s]);
                __syncthreads();
            }
            float rm = sv[0]; __syncthreads();
            // pass 2: sum exp (same stride + tree as verified kernel)
            float sum = 0.0f;
            for (int v = tid; v < V; v += NT) sum += expf(rowp[v] - rm);
            sv[tid] = sum; __syncthreads();
            for (int s = 128; s > 0; s >>= 1) {
                if (tid < s) sv[tid] += sv[tid + s];
                __syncthreads();
            }
            float ls = logf(sv[0]); __syncthreads();
            // eps draw for this row: bits = o0^o1 of tf(ke; 0, row)
            uint32_t db0, db1;
            tf2x32(ke0, ke1, 0u, (uint32_t)row, db0, db1);
            int draw = (eps >= u01(db0 ^ db1)) ? 1 : 0;
            // pass 3: gumbel + argmax. bits(b,v) = o0^o1 of tf(kg; 0, b*V+v)
            float best = -INFINITY; int bi = V;
            for (int v = tid; v < V; v += NT) {
                uint32_t n = (uint32_t)row * (uint32_t)V + (uint32_t)v;
                uint32_t o0, o1;
                tf2x32(kg0, kg1, 0u, n, o0, o1);
                float u = u01(o0 ^ o1); if (u == 0.0f) u = TINY;
                float g = -logf(-logf(u));
                float val = (draw ? NLU : ((rowp[v] - rm) - ls)) + g;
                if (val > best) { best = val; bi = v; }
            }
            sv[tid] = best; si[tid] = bi; __syncthreads();
            for (int s = 128; s > 0; s >>= 1) {
                if (tid < s) {
                    float v2 = sv[tid+s]; int i2 = si[tid+s];
                    if (v2 > sv[tid] || (v2 == sv[tid] && i2 < si[tid])) { sv[tid]=v2; si[tid]=i2; }
                }
                __syncthreads();
            }
            int samp = si[0];
            if (tid == 0) {
                float lp = (rowp[samp] - rm) - ls;
                out[(size_t)row * S + t]                   = (float)samp;
                out[(size_t)B * S + (size_t)row * S + t]   = lp;
            }
            // next-step input embedding (E == NT == 256)
            g_x[(size_t)row * E + tid] = emb[(size_t)samp * E + tid];
            __syncthreads();
        }
        gsync(epoch);
    }
}

// ---------------- launch: exactly 2 graph nodes -----------------------------
extern "C" void kernel_launch(void* const* d_in, const int* in_sizes, int n_in,
                              void* d_out, int out_size) {
    const float* emb   = (const float*)d_in[0];
    const float* w_ih  = (const float*)d_in[1];
    const float* w_hh  = (const float*)d_in[2];
    const float* b_ih  = (const float*)d_in[3];
    const float* b_hh  = (const float*)d_in[4];
    const float* w_out = (const float*)d_in[5];
    const float* b_out = (const float*)d_in[6];
    float* out = (float*)d_out;

    init_kernel<<<(B*H + 255)/256, 256>>>(emb);
    actor_persistent<<<GRID, NT>>>(emb, w_ih, w_hh, b_ih, b_hh, w_out, b_out, out);
}

// round 15
// speedup vs baseline: 1.3246x; 1.0303x over previous
#include <cuda_runtime.h>
#include <cstdint>
#include <math.h>

#define V 32000
#define E 256
#define H 512
#define B 512
#define S 256
#define G3 (3*H)

#define GRID 148
#define NT   256

// ---------------- device scratch (static globals: no allocs allowed) --------
__device__ float g_h[B*H];
__device__ float g_x[B*E];
__device__ float g_gi[B*G3];
__device__ float g_gh[B*G3];
__device__ float g_logits[B*V];       // 65.5 MB
__device__ unsigned g_stepkeys[S*2];
__device__ unsigned g_barrier_count;

// ---------------- packed f32x2 helpers (sm_103a FFMA2 path) -----------------
__device__ __forceinline__ unsigned long long f32x2_fma(unsigned long long a,
                                                        unsigned long long b,
                                                        unsigned long long c) {
    unsigned long long d;
    asm("fma.rn.f32x2 %0, %1, %2, %3;" : "=l"(d) : "l"(a), "l"(b), "l"(c));
    return d;
}
__device__ __forceinline__ unsigned long long f32x2_pack(float lo, float hi) {
    unsigned long long d;
    asm("mov.b64 %0, {%1, %2};" : "=l"(d) : "f"(lo), "f"(hi));
    return d;
}
__device__ __forceinline__ void f32x2_unpack(float& lo, float& hi, unsigned long long v) {
    asm("mov.b64 {%0, %1}, %2;" : "=f"(lo), "=f"(hi) : "l"(v));
}

// ---------------- Threefry-2x32 (exactly JAX's) -----------------------------
__device__ __forceinline__ void tf2x32(uint32_t k0, uint32_t k1,
                                       uint32_t x0, uint32_t x1,
                                       uint32_t& o0, uint32_t& o1) {
    uint32_t k2 = k0 ^ k1 ^ 0x1BD11BDAu;
    x0 += k0; x1 += k1;
#define TFRND(r) { x0 += x1; x1 = __funnelshift_l(x1, x1, r); x1 ^= x0; }
    TFRND(13) TFRND(15) TFRND(26) TFRND(6)
    x0 += k1; x1 += k2 + 1u;
    TFRND(17) TFRND(29) TFRND(16) TFRND(24)
    x0 += k2; x1 += k0 + 2u;
    TFRND(13) TFRND(15) TFRND(26) TFRND(6)
    x0 += k0; x1 += k1 + 3u;
    TFRND(17) TFRND(29) TFRND(16) TFRND(24)
    x0 += k1; x1 += k2 + 4u;
    TFRND(13) TFRND(15) TFRND(26) TFRND(6)
    x0 += k2; x1 += k0 + 5u;
#undef TFRND
    o0 = x0; o1 = x1;
}

__device__ __forceinline__ float u01(uint32_t bits) {
    return __uint_as_float((bits >> 9) | 0x3f800000u) - 1.0f;
}

// ---------------- init: h=0, x=emb[0] broadcast, per-step keys --------------
// jax_threefry_partitionable=True: split(key(42),S): key_t = tf((0,42); ctr=t)
__global__ void init_kernel(const float* __restrict__ emb) {
    int idx = blockIdx.x * blockDim.x + threadIdx.x;
    if (idx == 0) g_barrier_count = 0u;
    if (idx < B*H) g_h[idx] = 0.0f;
    if (idx < B*E) g_x[idx] = emb[idx % E];   // start token id 0
    if (idx < S) {
        uint32_t o0, o1;
        tf2x32(0u, 42u, 0u, (uint32_t)idx, o0, o1);
        g_stepkeys[2*idx]   = o0;
        g_stepkeys[2*idx+1] = o1;
    }
}

// ---------------- grid-wide software barrier --------------------------------
__device__ __forceinline__ void gsync(unsigned &epoch) {
    epoch += 1u;
    __syncthreads();
    if (threadIdx.x == 0) {
        __threadfence();               // release prior global writes
        atomicAdd(&g_barrier_count, 1u);
        unsigned tgt = epoch * GRID;
        while (atomicAdd(&g_barrier_count, 0u) < tgt) __nanosleep(64);
        __threadfence();               // acquire
    }
    __syncthreads();
}

// ---------------- 64x64 tile SGEMM (gates), 256 thr, 4x4/thread (R9) --------
__device__ void gemm_tile64(const float* __restrict__ A, const float* __restrict__ W,
                            const float* __restrict__ bias, float* __restrict__ C,
                            int N, int K, int bm, int bn, float* As, float* Bs) {
    const int tid = threadIdx.x;
    const int tx = tid % 16, ty = tid / 16;
    float acc[4][4];
#pragma unroll
    for (int i = 0; i < 4; i++)
#pragma unroll
        for (int j = 0; j < 4; j++) acc[i][j] = 0.0f;

    const int r = tid / 4, c4 = tid % 4;      // 64 rows x 4 float4-cols
#pragma unroll 1
    for (int k0 = 0; k0 < K; k0 += 16) {
        {
            float4 v = *(const float4*)(A + (size_t)(bm + r) * K + k0 + c4 * 4);
            As[(c4*4+0)*64 + r] = v.x; As[(c4*4+1)*64 + r] = v.y;
            As[(c4*4+2)*64 + r] = v.z; As[(c4*4+3)*64 + r] = v.w;
            float4 w = *(const float4*)(W + (size_t)(bn + r) * K + k0 + c4 * 4);
            Bs[(c4*4+0)*64 + r] = w.x; Bs[(c4*4+1)*64 + r] = w.y;
            Bs[(c4*4+2)*64 + r] = w.z; Bs[(c4*4+3)*64 + r] = w.w;
        }
        __syncthreads();
#pragma unroll
        for (int kk = 0; kk < 16; kk++) {
            float4 a = *(const float4*)&As[kk*64 + ty*4];
            float4 b = *(const float4*)&Bs[kk*64 + tx*4];
            float ar[4] = {a.x, a.y, a.z, a.w};
            float br[4] = {b.x, b.y, b.z, b.w};
#pragma unroll
            for (int i = 0; i < 4; i++)
#pragma unroll
                for (int j = 0; j < 4; j++) acc[i][j] = fmaf(ar[i], br[j], acc[i][j]);
        }
        __syncthreads();
    }
#pragma unroll
    for (int i = 0; i < 4; i++) {
        int m = bm + ty*4 + i;
#pragma unroll
        for (int j = 0; j < 4; j++) {
            int n = bn + tx*4 + j;
            C[(size_t)m * N + n] = acc[i][j] + bias[n];
        }
    }
}

// ---------------- 128x128 tile SGEMM (logits), f32x2 packed FMA core --------
// acc2[i][jp] packs output columns (2jp, 2jp+1) of row i. Each packed lane is
// an independent IEEE RN fma => per-element accumulation bit-identical to the
// scalar version (kk ascending within k-tile, k-tiles ascending).
__device__ void gemm_tile128(const float* __restrict__ A, const float* __restrict__ W,
                             const float* __restrict__ bias, float* __restrict__ C,
                             int bm, int bn, float* As, float* Bs) {
    const int K = H;                          // 512
    const int tid = threadIdx.x;
    const int tx = tid % 16, ty = tid / 16;   // each thread 8x8
    unsigned long long acc2[8][4];
#pragma unroll
    for (int i = 0; i < 8; i++)
#pragma unroll
        for (int j = 0; j < 4; j++) acc2[i][j] = 0ULL;

    const int r0 = tid / 4, c0 = tid % 4;
    const int r1 = r0 + 64;

    {   // preload k-tile 0
        float4 a0 = *(const float4*)(A + (size_t)(bm + r0) * K + c0 * 4);
        float4 a1 = *(const float4*)(A + (size_t)(bm + r1) * K + c0 * 4);
        float4 w0 = *(const float4*)(W + (size_t)(bn + r0) * K + c0 * 4);
        float4 w1 = *(const float4*)(W + (size_t)(bn + r1) * K + c0 * 4);
        As[(c0*4+0)*128 + r0] = a0.x; As[(c0*4+1)*128 + r0] = a0.y;
        As[(c0*4+2)*128 + r0] = a0.z; As[(c0*4+3)*128 + r0] = a0.w;
        As[(c0*4+0)*128 + r1] = a1.x; As[(c0*4+1)*128 + r1] = a1.y;
        As[(c0*4+2)*128 + r1] = a1.z; As[(c0*4+3)*128 + r1] = a1.w;
        Bs[(c0*4+0)*128 + r0] = w0.x; Bs[(c0*4+1)*128 + r0] = w0.y;
        Bs[(c0*4+2)*128 + r0] = w0.z; Bs[(c0*4+3)*128 + r0] = w0.w;
        Bs[(c0*4+0)*128 + r1] = w1.x; Bs[(c0*4+1)*128 + r1] = w1.y;
        Bs[(c0*4+2)*128 + r1] = w1.z; Bs[(c0*4+3)*128 + r1] = w1.w;
    }
    __syncthreads();

#pragma unroll 1
    for (int k0 = 0; k0 < K; k0 += 16) {
        float4 pa0, pa1, pb0, pb1;
        const bool more = (k0 + 16) < K;
        if (more) {
            pa0 = *(const float4*)(A + (size_t)(bm + r0) * K + k0 + 16 + c0 * 4);
            pa1 = *(const float4*)(A + (size_t)(bm + r1) * K + k0 + 16 + c0 * 4);
            pb0 = *(const float4*)(W + (size_t)(bn + r0) * K + k0 + 16 + c0 * 4);
            pb1 = *(const float4*)(W + (size_t)(bn + r1) * K + k0 + 16 + c0 * 4);
        }
#pragma unroll
        for (int kk = 0; kk < 16; kk++) {
            float4 a0 = *(const float4*)&As[kk*128 + ty*8];
            float4 a1 = *(const float4*)&As[kk*128 + ty*8 + 4];
            float4 b0 = *(const float4*)&Bs[kk*128 + tx*8];
            float4 b1 = *(const float4*)&Bs[kk*128 + tx*8 + 4];
            unsigned long long bb[4] = {
                f32x2_pack(b0.x, b0.y), f32x2_pack(b0.z, b0.w),
                f32x2_pack(b1.x, b1.y), f32x2_pack(b1.z, b1.w)
            };
            float ar[8] = {a0.x,a0.y,a0.z,a0.w,a1.x,a1.y,a1.z,a1.w};
#pragma unroll
            for (int i = 0; i < 8; i++) {
                unsigned long long aa = f32x2_pack(ar[i], ar[i]);
#pragma unroll
                for (int j = 0; j < 4; j++)
                    acc2[i][j] = f32x2_fma(aa, bb[j], acc2[i][j]);
            }
        }
        __syncthreads();
        if (more) {
            As[(c0*4+0)*128 + r0] = pa0.x; As[(c0*4+1)*128 + r0] = pa0.y;
            As[(c0*4+2)*128 + r0] = pa0.z; As[(c0*4+3)*128 + r0] = pa0.w;
            As[(c0*4+0)*128 + r1] = pa1.x; As[(c0*4+1)*128 + r1] = pa1.y;
            As[(c0*4+2)*128 + r1] = pa1.z; As[(c0*4+3)*128 + r1] = pa1.w;
            Bs[(c0*4+0)*128 + r0] = pb0.x; Bs[(c0*4+1)*128 + r0] = pb0.y;
            Bs[(c0*4+2)*128 + r0] = pb0.z; Bs[(c0*4+3)*128 + r0] = pb0.w;
            Bs[(c0*4+0)*128 + r1] = pb1.x; Bs[(c0*4+1)*128 + r1] = pb1.y;
            Bs[(c0*4+2)*128 + r1] = pb1.z; Bs[(c0*4+3)*128 + r1] = pb1.w;
        }
        __syncthreads();
    }
#pragma unroll
    for (int i = 0; i < 8; i++) {
        int m = bm + ty*8 + i;
#pragma unroll
        for (int j = 0; j < 4; j++) {
            float lo, hi;
            f32x2_unpack(lo, hi, acc2[i][j]);
            int n = bn + tx*8 + 2*j;
            C[(size_t)m * V + n]     = lo + bias[n];
            C[(size_t)m * V + n + 1] = hi + bias[n + 1];
        }
    }
}

// ---------------- persistent kernel -----------------------------------------
__global__ __launch_bounds__(NT, 1)
void actor_persistent(const float* __restrict__ emb,
                      const float* __restrict__ w_ih, const float* __restrict__ w_hh,
                      const float* __restrict__ b_ih, const float* __restrict__ b_hh,
                      const float* __restrict__ w_out, const float* __restrict__ b_out,
                      float* __restrict__ out) {
    __shared__ __align__(16) float sh[4096];   // As = sh, Bs = sh+2048
    __shared__ float sv[NT];
    __shared__ int   si[NT];

    const int tid = threadIdx.x;
    unsigned epoch = 0;
    const float NLU  = -10.373491181781864f;   // -float32(log(32000))
    const float TINY = 1.1754943508222875e-38f;

    for (int t = 0; t < S; t++) {
        // ---- Phase A: gate GEMMs gi = x@w_ih^T+b_ih, gh = h@w_hh^T+b_hh ----
        for (int tile = blockIdx.x; tile < 384; tile += GRID) {
            if (tile < 192) {
                int bm = (tile / 24) * 64, bn = (tile % 24) * 64;
                gemm_tile64(g_x, w_ih, b_ih, g_gi, G3, E, bm, bn, sh, sh + 2048);
            } else {
                int tt = tile - 192;
                int bm = (tt / 24) * 64, bn = (tt % 24) * 64;
                gemm_tile64(g_h, w_hh, b_hh, g_gh, G3, H, bm, bn, sh, sh + 2048);
            }
        }
        gsync(epoch);

        // ---- Phase B: GRU combine (elementwise, exact) ----
        for (int idx = blockIdx.x * NT + tid; idx < B*H; idx += GRID * NT) {
            int b = idx / H, j = idx % H;
            const float* gi = g_gi + (size_t)b * G3;
            const float* gh = g_gh + (size_t)b * G3;
            float i_r = gi[j],        h_r = gh[j];
            float i_z = gi[H + j],    h_z = gh[H + j];
            float i_n = gi[2*H + j],  h_n = gh[2*H + j];
            float r = 1.0f / (1.0f + expf(-(i_r + h_r)));
            float z = 1.0f / (1.0f + expf(-(i_z + h_z)));
            float n = tanhf(i_n + r * h_n);
            float h_old = g_h[idx];
            g_h[idx] = (1.0f - z) * n + z * h_old;
        }
        gsync(epoch);

        // ---- Phase C: logits GEMM (512 x 32000, K=512) ----
        for (int tile = blockIdx.x; tile < 1000; tile += GRID) {
            int bm = (tile % 4) * 128, bn = (tile / 4) * 128;
            gemm_tile128(g_h, w_out, b_out, g_logits, bm, bn, sh, sh + 2048);
        }
        gsync(epoch);

        // ---- Phase D: per-row stats + gumbel sample (foldlike RNG) ----
        uint32_t kt0 = g_stepkeys[2*t], kt1 = g_stepkeys[2*t+1];
        uint32_t ke0, ke1, kg0, kg1;
        tf2x32(kt0, kt1, 0u, 0u, ke0, ke1);
        tf2x32(kt0, kt1, 0u, 1u, kg0, kg1);
        float eps = 0.05f + 0.95f * expf(-4.0f * (float)t / 10000.0f);

        for (int row = blockIdx.x; row < B; row += GRID) {
            const float* rowp = g_logits + (size_t)row * V;
            // pass 1: row max (order-exact under any partition)
            float m = -INFINITY;
            for (int v = tid; v < V; v += NT) m = fmaxf(m, rowp[v]);
            sv[tid] = m; __syncthreads();
            for (int s = 128; s > 0; s >>= 1) {
                if (tid < s) sv[tid] = fmaxf(sv[tid], sv[tid + s]);
                __syncthreads();
            }
            float rm = sv[0]; __syncthreads();
            // pass 2: sum exp (same stride + tree as verified kernel => exact)
            float sum = 0.0f;
            for (int v = tid; v < V; v += NT) sum += expf(rowp[v] - rm);
            sv[tid] = sum; __syncthreads();
            for (int s = 128; s > 0; s >>= 1) {
                if (tid < s) sv[tid] += sv[tid + s];
                __syncthreads();
            }
            float ls = logf(sv[0]); __syncthreads();
            // eps draw for this row: bits = o0^o1 of tf(ke; 0, row)
            uint32_t db0, db1;
            tf2x32(ke0, ke1, 0u, (uint32_t)row, db0, db1);
            int draw = (eps >= u01(db0 ^ db1)) ? 1 : 0;
            // pass 3: gumbel + argmax, TWO independent streams per thread for
            // ILP on the serial threefry/log chains. Stream 0 covers
            // k in [0,63) (indices tid+k*NT < 16128); stream 1 covers
            // k in [63,125) (indices >= 16128). All stream-0 indices are less
            // than all stream-1 indices, so the strict-> merge below preserves
            // jnp.argmax's first-index tie-break.
            float best0 = -INFINITY, best1 = -INFINITY;
            int bi0 = V, bi1 = V;
#pragma unroll 1
            for (int k = 0; k < 63; k++) {
                int v0 = tid + k * NT;
                uint32_t n0 = (uint32_t)row * (uint32_t)V + (uint32_t)v0;
                uint32_t o0, o1;
                tf2x32(kg0, kg1, 0u, n0, o0, o1);
                float u0 = u01(o0 ^ o1); if (u0 == 0.0f) u0 = TINY;
                float g0 = -logf(-logf(u0));
                float val0 = (draw ? NLU : ((rowp[v0] - rm) - ls)) + g0;
                if (val0 > best0) { best0 = val0; bi0 = v0; }
                if (k < 62) {
                    int v1 = tid + (63 + k) * NT;
                    uint32_t n1 = (uint32_t)row * (uint32_t)V + (uint32_t)v1;
                    uint32_t p0, p1;
                    tf2x32(kg0, kg1, 0u, n1, p0, p1);
                    float u1 = u01(p0 ^ p1); if (u1 == 0.0f) u1 = TINY;
                    float g1 = -logf(-logf(u1));
                    float val1 = (draw ? NLU : ((rowp[v1] - rm) - ls)) + g1;
                    if (val1 > best1) { best1 = val1; bi1 = v1; }
                }
            }
            float best = best0; int bi = bi0;
            if (best1 > best) { best = best1; bi = bi1; }
            sv[tid] = best; si[tid] = bi; __syncthreads();
            for (int s = 128; s > 0; s >>= 1) {
                if (tid < s) {
                    float v2 = sv[tid+s]; int i2 = si[tid+s];
                    if (v2 > sv[tid] || (v2 == sv[tid] && i2 < si[tid])) { sv[tid]=v2; si[tid]=i2; }
                }
                __syncthreads();
            }
            int samp = si[0];
            if (tid == 0) {
                float lp = (rowp[samp] - rm) - ls;
                out[(size_t)row * S + t]                   = (float)samp;
                out[(size_t)B * S + (size_t)row * S + t]   = lp;
            }
            // next-step input embedding (E == NT == 256)
            g_x[(size_t)row * E + tid] = emb[(size_t)samp * E + tid];
            __syncthreads();
        }
        gsync(epoch);
    }
}

// ---------------- launch: exactly 2 graph nodes -----------------------------
extern "C" void kernel_launch(void* const* d_in, const int* in_sizes, int n_in,
                              void* d_out, int out_size) {
    const float* emb   = (const float*)d_in[0];
    const float* w_ih  = (const float*)d_in[1];
    const float* w_hh  = (const float*)d_in[2];
    const float* b_ih  = (const float*)d_in[3];
    const float* b_hh  = (const float*)d_in[4];
    const float* w_out = (const float*)d_in[5];
    const float* b_out = (const float*)d_in[6];
    float* out = (float*)d_out;

    init_kernel<<<(B*H + 255)/256, 256>>>(emb);
    actor_persistent<<<GRID, NT>>>(emb, w_ih, w_hh, b_ih, b_hh, w_out, b_out, out);
}